// round 2
// baseline (speedup 1.0000x reference)
#include <cuda_runtime.h>
#include <cuda_bf16.h>
#include <cstdint>

// ============================================================================
// Problem constants
// ============================================================================
#define NROWS 16384
#define DDIM  256
#define INV_T 14.285714285714286f   // 1 / 0.07

// SMEM tile geometry: stride padded to kill bank conflicts (264*2 = 528 B rows)
#define STRIDE  264
#define TILE_BYTES (128 * STRIDE * 2)   // 67584 per 128x256 bf16 tile
#define SMEM_DYN_BYTES (3 * TILE_BYTES + 1024)

// ============================================================================
// Device scratch (allocation-free rule: __device__ globals)
// ============================================================================
__device__ __nv_bfloat16 g_Vn[(size_t)NROWS * DDIM];  // normalized img, bf16
__device__ __nv_bfloat16 g_Un[(size_t)NROWS * DDIM];  // normalized txt, bf16
__device__ float g_rowsum[NROWS];  // sum_j exp(sim_ij - 1/T)
__device__ float g_colsum[NROWS];  // sum_i exp(sim_ij - 1/T)
__device__ float g_diag[NROWS];    // cos(v_i, u_i), exact fp32

// ============================================================================
// PTX helpers (all baseline sm_80/sm_90 features -> legal under compute_103)
// ============================================================================
__device__ __forceinline__ uint32_t smem_u32(const void* p) {
    uint32_t a;
    asm("{ .reg .u64 t; cvta.to.shared.u64 t, %1; cvt.u32.u64 %0, t; }"
        : "=r"(a) : "l"(p));
    return a;
}

#define CP_ASYNC16(dst_u32, src_ptr) \
    asm volatile("cp.async.cg.shared.global [%0], [%1], 16;" \
        :: "r"(dst_u32), "l"(src_ptr) : "memory")
#define CP_ASYNC_COMMIT() asm volatile("cp.async.commit_group;" ::: "memory")
#define CP_ASYNC_WAIT_1() asm volatile("cp.async.wait_group 1;" ::: "memory")
#define CP_ASYNC_WAIT_0() asm volatile("cp.async.wait_group 0;" ::: "memory")

__device__ __forceinline__ void ldsm4(uint32_t* r, uint32_t addr) {
    asm volatile("ldmatrix.sync.aligned.m8n8.x4.shared.b16 {%0,%1,%2,%3}, [%4];"
        : "=r"(r[0]), "=r"(r[1]), "=r"(r[2]), "=r"(r[3]) : "r"(addr));
}

__device__ __forceinline__ void mma_bf16(float* c, const uint32_t* a, const uint32_t* b) {
    asm volatile(
        "mma.sync.aligned.m16n8k16.row.col.f32.bf16.bf16.f32 "
        "{%0,%1,%2,%3}, {%4,%5,%6,%7}, {%8,%9}, {%0,%1,%2,%3};"
        : "+f"(c[0]), "+f"(c[1]), "+f"(c[2]), "+f"(c[3])
        : "r"(a[0]), "r"(a[1]), "r"(a[2]), "r"(a[3]), "r"(b[0]), "r"(b[1]));
}

// ============================================================================
// Kernel A: per-row L2 normalize (fp32 math -> bf16), diag cos, zero accums
// ============================================================================
__global__ __launch_bounds__(256) void normalize_kernel(
    const float* __restrict__ img, const float* __restrict__ txt)
{
    int warp = threadIdx.x >> 5, lane = threadIdx.x & 31;
    int row = blockIdx.x * 8 + warp;

    const float4* v4 = reinterpret_cast<const float4*>(img) + (size_t)row * (DDIM / 4) + lane * 2;
    const float4* u4 = reinterpret_cast<const float4*>(txt) + (size_t)row * (DDIM / 4) + lane * 2;
    float4 a0 = v4[0], a1 = v4[1];
    float4 b0 = u4[0], b1 = u4[1];

    float sv = a0.x*a0.x + a0.y*a0.y + a0.z*a0.z + a0.w*a0.w
             + a1.x*a1.x + a1.y*a1.y + a1.z*a1.z + a1.w*a1.w;
    float su = b0.x*b0.x + b0.y*b0.y + b0.z*b0.z + b0.w*b0.w
             + b1.x*b1.x + b1.y*b1.y + b1.z*b1.z + b1.w*b1.w;
    float dv = a0.x*b0.x + a0.y*b0.y + a0.z*b0.z + a0.w*b0.w
             + a1.x*b1.x + a1.y*b1.y + a1.z*b1.z + a1.w*b1.w;

    #pragma unroll
    for (int s = 16; s > 0; s >>= 1) {
        sv += __shfl_xor_sync(0xffffffffu, sv, s);
        su += __shfl_xor_sync(0xffffffffu, su, s);
        dv += __shfl_xor_sync(0xffffffffu, dv, s);
    }

    float inv_v = 1.0f / fmaxf(sqrtf(sv), 1e-8f);
    float inv_u = 1.0f / fmaxf(sqrtf(su), 1e-8f);

    if (lane == 0) {
        g_diag[row]   = dv * inv_v * inv_u;
        g_rowsum[row] = 0.0f;
        g_colsum[row] = 0.0f;
    }

    __nv_bfloat162 p0 = __floats2bfloat162_rn(a0.x*inv_v, a0.y*inv_v);
    __nv_bfloat162 p1 = __floats2bfloat162_rn(a0.z*inv_v, a0.w*inv_v);
    __nv_bfloat162 p2 = __floats2bfloat162_rn(a1.x*inv_v, a1.y*inv_v);
    __nv_bfloat162 p3 = __floats2bfloat162_rn(a1.z*inv_v, a1.w*inv_v);
    uint4 pk;
    pk.x = *reinterpret_cast<uint32_t*>(&p0);
    pk.y = *reinterpret_cast<uint32_t*>(&p1);
    pk.z = *reinterpret_cast<uint32_t*>(&p2);
    pk.w = *reinterpret_cast<uint32_t*>(&p3);
    reinterpret_cast<uint4*>(g_Vn)[(size_t)row * (DDIM / 8) + lane] = pk;

    __nv_bfloat162 q0 = __floats2bfloat162_rn(b0.x*inv_u, b0.y*inv_u);
    __nv_bfloat162 q1 = __floats2bfloat162_rn(b0.z*inv_u, b0.w*inv_u);
    __nv_bfloat162 q2 = __floats2bfloat162_rn(b1.x*inv_u, b1.y*inv_u);
    __nv_bfloat162 q3 = __floats2bfloat162_rn(b1.z*inv_u, b1.w*inv_u);
    uint4 qk;
    qk.x = *reinterpret_cast<uint32_t*>(&q0);
    qk.y = *reinterpret_cast<uint32_t*>(&q1);
    qk.z = *reinterpret_cast<uint32_t*>(&q2);
    qk.w = *reinterpret_cast<uint32_t*>(&q3);
    reinterpret_cast<uint4*>(g_Un)[(size_t)row * (DDIM / 8) + lane] = qk;
}

// ============================================================================
// Kernel B: fused mma.sync GEMM (128x128 per tile, 2 N-tiles per CTA, K=256)
// + exp + row/col partial sums.
// 8 warps: warp_m = wid&3 (32 rows), warp_n = wid>>2 (64 cols).
// ============================================================================
__global__ __launch_bounds__(256, 1) void simloss_mma_kernel()
{
    extern __shared__ __align__(16) char sm[];
    char* As  = sm;                       // 128 x 256 bf16, stride 264
    float* rowbuf = reinterpret_cast<float*>(sm + 3 * TILE_BYTES);
    float* colbuf = rowbuf + 128;

    int tid = threadIdx.x, lane = tid & 31, wid = tid >> 5;
    int warp_m = wid & 3, warp_n = wid >> 2;
    int bm = blockIdx.y;        // row-tile (V rows)
    int bx = blockIdx.x;        // pair of column-tiles (U rows)

    if (tid < 128) { rowbuf[tid] = 0.0f; colbuf[tid] = 0.0f; }

    // ---- async loads: A + B0 (group old), B1 (group new) ----
    const char* Ag = reinterpret_cast<const char*>(g_Vn + (size_t)bm * 128 * DDIM);
    const char* Bg = reinterpret_cast<const char*>(g_Un + (size_t)bx * 256 * DDIM);
    uint32_t As_u  = smem_u32(As);
    uint32_t Bs_u0 = As_u + TILE_BYTES;
    uint32_t Bs_u1 = As_u + 2 * TILE_BYTES;

    #pragma unroll
    for (int it = 0; it < 16; it++) {
        int i = it * 256 + tid;
        int row = i >> 5, c = i & 31;
        uint32_t soff = row * 528 + c * 16;
        uint32_t goff = row * 512 + c * 16;
        CP_ASYNC16(As_u  + soff, Ag + goff);
        CP_ASYNC16(Bs_u0 + soff, Bg + goff);
    }
    CP_ASYNC_COMMIT();
    #pragma unroll
    for (int it = 0; it < 16; it++) {
        int i = it * 256 + tid;
        int row = i >> 5, c = i & 31;
        CP_ASYNC16(Bs_u1 + row * 528 + c * 16, Bg + 65536 + row * 512 + c * 16);
    }
    CP_ASYNC_COMMIT();

    // ldmatrix per-lane base addresses
    // A: lanes 0-15 rows m0..m15 @k0 ; 16-31 rows @k+8
    uint32_t a_base = As_u +
        ((warp_m * 32 + (lane & 15)) * STRIDE + (lane >> 4) * 8) * 2;
    // B: row = (lane&7) + ((lane>>4)<<3), khalf = (lane>>3)&1
    uint32_t b_lane_off =
        (((lane & 7) + ((lane >> 4) << 3) + warp_n * 64) * STRIDE + ((lane >> 3) & 1) * 8) * 2;

    #pragma unroll 1
    for (int t = 0; t < 2; t++) {
        if (t == 0) { CP_ASYNC_WAIT_1(); } else { CP_ASYNC_WAIT_0(); }
        __syncthreads();

        uint32_t b_base = (t == 0 ? Bs_u0 : Bs_u1) + b_lane_off;

        // ---- mainloop: K = 256 = 16 k-steps of 16 ----
        float acc[64];
        #pragma unroll
        for (int i = 0; i < 64; i++) acc[i] = 0.0f;

        #pragma unroll
        for (int ks = 0; ks < 16; ks++) {
            uint32_t a[2][4];
            ldsm4(a[0], a_base + ks * 32);
            ldsm4(a[1], a_base + ks * 32 + 16 * STRIDE * 2);
            uint32_t b[4][4];
            #pragma unroll
            for (int p = 0; p < 4; p++)
                ldsm4(b[p], b_base + ks * 32 + p * 16 * STRIDE * 2);
            #pragma unroll
            for (int mt = 0; mt < 2; mt++)
                #pragma unroll
                for (int p = 0; p < 4; p++) {
                    mma_bf16(&acc[(mt * 8 + 2 * p) * 4],     a[mt], &b[p][0]);
                    mma_bf16(&acc[(mt * 8 + 2 * p + 1) * 4], a[mt], &b[p][2]);
                }
        }

        // ---- epilogue: exp + row/col partials ----
        // acc regs of one m16n8: c0 (row g, col 2u), c1 (row g, col 2u+1),
        // c2 (row g+8, col 2u), c3 (row g+8, col 2u+1); g=lane>>2, u=lane&3.
        float rp[4] = {0.f, 0.f, 0.f, 0.f};
        float cp0[8], cp1[8];
        #pragma unroll
        for (int nt = 0; nt < 8; nt++) { cp0[nt] = 0.f; cp1[nt] = 0.f; }

        #pragma unroll
        for (int mt = 0; mt < 2; mt++)
            #pragma unroll
            for (int nt = 0; nt < 8; nt++) {
                float* c = &acc[(mt * 8 + nt) * 4];
                float e0 = __expf((c[0] - 1.0f) * INV_T);
                float e1 = __expf((c[1] - 1.0f) * INV_T);
                float e2 = __expf((c[2] - 1.0f) * INV_T);
                float e3 = __expf((c[3] - 1.0f) * INV_T);
                rp[mt * 2 + 0] += e0 + e1;
                rp[mt * 2 + 1] += e2 + e3;
                cp0[nt] += e0 + e2;
                cp1[nt] += e1 + e3;
            }

        // reduce rows across the 4 lanes sharing g
        #pragma unroll
        for (int s = 1; s <= 2; s <<= 1) {
            rp[0] += __shfl_xor_sync(0xffffffffu, rp[0], s);
            rp[1] += __shfl_xor_sync(0xffffffffu, rp[1], s);
            rp[2] += __shfl_xor_sync(0xffffffffu, rp[2], s);
            rp[3] += __shfl_xor_sync(0xffffffffu, rp[3], s);
        }
        if ((lane & 3) == 0) {
            int g = lane >> 2;
            atomicAdd(&rowbuf[warp_m * 32 + g],      rp[0]);
            atomicAdd(&rowbuf[warp_m * 32 + 8 + g],  rp[1]);
            atomicAdd(&rowbuf[warp_m * 32 + 16 + g], rp[2]);
            atomicAdd(&rowbuf[warp_m * 32 + 24 + g], rp[3]);
        }

        // reduce cols across the 8 g-groups (lanes differing in bits 2..4)
        #pragma unroll
        for (int s = 4; s <= 16; s <<= 1)
            #pragma unroll
            for (int nt = 0; nt < 8; nt++) {
                cp0[nt] += __shfl_xor_sync(0xffffffffu, cp0[nt], s);
                cp1[nt] += __shfl_xor_sync(0xffffffffu, cp1[nt], s);
            }
        if (lane < 4) {
            int u = lane;
            #pragma unroll
            for (int nt = 0; nt < 8; nt++) {
                atomicAdd(&colbuf[warp_n * 64 + nt * 8 + 2 * u],     cp0[nt]);
                atomicAdd(&colbuf[warp_n * 64 + nt * 8 + 2 * u + 1], cp1[nt]);
            }
        }

        __syncthreads();
        if (tid < 128) {
            atomicAdd(&g_colsum[bx * 256 + t * 128 + tid], colbuf[tid]);
            colbuf[tid] = 0.0f;
        }
        __syncthreads();
    }

    if (tid < 128)
        atomicAdd(&g_rowsum[bm * 128 + tid], rowbuf[tid]);
}

// ============================================================================
// Kernel C: finalize. loss = 1/T + mean(log sum) - (1/T)*mean(diag)
// ============================================================================
__global__ __launch_bounds__(256) void finalize_kernel(float* __restrict__ out)
{
    __shared__ float red_lv[8], red_lu[8], red_d[8];
    int tid = threadIdx.x, lane = tid & 31, warp = tid >> 5;

    float slv = 0.0f, slu = 0.0f, sd = 0.0f;
    for (int i = tid; i < NROWS; i += 256) {
        slv += logf(g_rowsum[i]);
        slu += logf(g_colsum[i]);
        sd  += g_diag[i];
    }
    #pragma unroll
    for (int s = 16; s > 0; s >>= 1) {
        slv += __shfl_xor_sync(0xffffffffu, slv, s);
        slu += __shfl_xor_sync(0xffffffffu, slu, s);
        sd  += __shfl_xor_sync(0xffffffffu, sd,  s);
    }
    if (lane == 0) { red_lv[warp] = slv; red_lu[warp] = slu; red_d[warp] = sd; }
    __syncthreads();
    if (tid == 0) {
        float tlv = 0.0f, tlu = 0.0f, td = 0.0f;
        #pragma unroll
        for (int w = 0; w < 8; w++) { tlv += red_lv[w]; tlu += red_lu[w]; td += red_d[w]; }
        float mlv = tlv * (1.0f / NROWS);
        float mlu = tlu * (1.0f / NROWS);
        float md  = td  * (1.0f / NROWS);
        float loss_vu = INV_T + mlv - INV_T * md;
        float loss_uv = INV_T + mlu - INV_T * md;
        out[0] = 0.5f * loss_vu + 0.5f * loss_uv;
        out[1] = loss_vu;
        out[2] = loss_uv;
    }
}

// ============================================================================
// Launch
// ============================================================================
extern "C" void kernel_launch(void* const* d_in, const int* in_sizes, int n_in,
                              void* d_out, int out_size)
{
    const float* img = (const float*)d_in[0];
    const float* txt = (const float*)d_in[1];
    float* out = (float*)d_out;

    cudaFuncSetAttribute(simloss_mma_kernel,
                         cudaFuncAttributeMaxDynamicSharedMemorySize, SMEM_DYN_BYTES);

    normalize_kernel<<<NROWS / 8, 256>>>(img, txt);
    simloss_mma_kernel<<<dim3(NROWS / 256, NROWS / 128), 256, SMEM_DYN_BYTES>>>();
    finalize_kernel<<<1, 256>>>(out);
}

// round 3
// speedup vs baseline: 1.2783x; 1.2783x over previous
#include <cuda_runtime.h>
#include <cuda_bf16.h>
#include <cuda_fp8.h>
#include <cstdint>

// ============================================================================
// Problem constants
// ============================================================================
#define NROWS 16384
#define DDIM  256
#define INV_T 14.285714285714286f        // 1 / 0.07
#define INV_T64 (INV_T / 64.0f)          // acc holds 64*sim (inputs scaled x8)

// SMEM tile geometry: fp8, 256 B/row padded to 272 B (odd multiple of 16B)
#define STRIDE_B 272
#define TILE_BYTES (128 * STRIDE_B)      // 34816 per 128x256 fp8 tile
#define SMEM_DYN_BYTES (3 * TILE_BYTES + 1024)

// ============================================================================
// Device scratch (allocation-free rule: __device__ globals)
// ============================================================================
__device__ uint8_t g_V8[(size_t)NROWS * DDIM];  // normalized img * 8, e4m3
__device__ uint8_t g_U8[(size_t)NROWS * DDIM];  // normalized txt * 8, e4m3
__device__ float g_rowsum[NROWS];  // sum_j exp(sim_ij - 1)/T-shifted
__device__ float g_colsum[NROWS];
__device__ float g_diag[NROWS];    // cos(v_i, u_i), exact fp32

// ============================================================================
// PTX helpers (baseline sm_80/sm_89 features -> legal under compute_103)
// ============================================================================
__device__ __forceinline__ uint32_t smem_u32(const void* p) {
    uint32_t a;
    asm("{ .reg .u64 t; cvta.to.shared.u64 t, %1; cvt.u32.u64 %0, t; }"
        : "=r"(a) : "l"(p));
    return a;
}

#define CP_ASYNC16(dst_u32, src_ptr) \
    asm volatile("cp.async.cg.shared.global [%0], [%1], 16;" \
        :: "r"(dst_u32), "l"(src_ptr) : "memory")
#define CP_ASYNC_COMMIT() asm volatile("cp.async.commit_group;" ::: "memory")
#define CP_ASYNC_WAIT_1() asm volatile("cp.async.wait_group 1;" ::: "memory")
#define CP_ASYNC_WAIT_0() asm volatile("cp.async.wait_group 0;" ::: "memory")

__device__ __forceinline__ void ldsm4(uint32_t* r, uint32_t addr) {
    asm volatile("ldmatrix.sync.aligned.m8n8.x4.shared.b16 {%0,%1,%2,%3}, [%4];"
        : "=r"(r[0]), "=r"(r[1]), "=r"(r[2]), "=r"(r[3]) : "r"(addr));
}

// fp8 e4m3 MMA, K=32 per instruction (2x MACs vs bf16 m16n8k16)
__device__ __forceinline__ void mma_fp8(float* c, const uint32_t* a, const uint32_t* b) {
    asm volatile(
        "mma.sync.aligned.m16n8k32.row.col.f32.e4m3.e4m3.f32 "
        "{%0,%1,%2,%3}, {%4,%5,%6,%7}, {%8,%9}, {%0,%1,%2,%3};"
        : "+f"(c[0]), "+f"(c[1]), "+f"(c[2]), "+f"(c[3])
        : "r"(a[0]), "r"(a[1]), "r"(a[2]), "r"(a[3]), "r"(b[0]), "r"(b[1]));
}

// ============================================================================
// Kernel A: per-row L2 normalize -> (8*v) as e4m3, diag cos, zero accums
// ============================================================================
__global__ __launch_bounds__(256) void normalize_kernel(
    const float* __restrict__ img, const float* __restrict__ txt)
{
    int warp = threadIdx.x >> 5, lane = threadIdx.x & 31;
    int row = blockIdx.x * 8 + warp;

    const float4* v4 = reinterpret_cast<const float4*>(img) + (size_t)row * (DDIM / 4) + lane * 2;
    const float4* u4 = reinterpret_cast<const float4*>(txt) + (size_t)row * (DDIM / 4) + lane * 2;
    float4 a0 = v4[0], a1 = v4[1];
    float4 b0 = u4[0], b1 = u4[1];

    float sv = a0.x*a0.x + a0.y*a0.y + a0.z*a0.z + a0.w*a0.w
             + a1.x*a1.x + a1.y*a1.y + a1.z*a1.z + a1.w*a1.w;
    float su = b0.x*b0.x + b0.y*b0.y + b0.z*b0.z + b0.w*b0.w
             + b1.x*b1.x + b1.y*b1.y + b1.z*b1.z + b1.w*b1.w;
    float dv = a0.x*b0.x + a0.y*b0.y + a0.z*b0.z + a0.w*b0.w
             + a1.x*b1.x + a1.y*b1.y + a1.z*b1.z + a1.w*b1.w;

    #pragma unroll
    for (int s = 16; s > 0; s >>= 1) {
        sv += __shfl_xor_sync(0xffffffffu, sv, s);
        su += __shfl_xor_sync(0xffffffffu, su, s);
        dv += __shfl_xor_sync(0xffffffffu, dv, s);
    }

    float inv_v = 8.0f / fmaxf(sqrtf(sv), 1e-8f);   // scale x8 into e4m3 range
    float inv_u = 8.0f / fmaxf(sqrtf(su), 1e-8f);

    if (lane == 0) {
        g_diag[row]   = dv * (inv_v * inv_u) * (1.0f / 64.0f);
        g_rowsum[row] = 0.0f;
        g_colsum[row] = 0.0f;
    }

    // pack 8 floats -> 8 e4m3 bytes (4x fp8x2 cvt)
    uint32_t w0, w1;
    {
        __nv_fp8x2_storage_t p0 = __nv_cvt_float2_to_fp8x2(
            make_float2(a0.x*inv_v, a0.y*inv_v), __NV_SATFINITE, __NV_E4M3);
        __nv_fp8x2_storage_t p1 = __nv_cvt_float2_to_fp8x2(
            make_float2(a0.z*inv_v, a0.w*inv_v), __NV_SATFINITE, __NV_E4M3);
        __nv_fp8x2_storage_t p2 = __nv_cvt_float2_to_fp8x2(
            make_float2(a1.x*inv_v, a1.y*inv_v), __NV_SATFINITE, __NV_E4M3);
        __nv_fp8x2_storage_t p3 = __nv_cvt_float2_to_fp8x2(
            make_float2(a1.z*inv_v, a1.w*inv_v), __NV_SATFINITE, __NV_E4M3);
        w0 = (uint32_t)p0 | ((uint32_t)p1 << 16);
        w1 = (uint32_t)p2 | ((uint32_t)p3 << 16);
    }
    reinterpret_cast<uint2*>(g_V8)[(size_t)row * (DDIM / 8) + lane] = make_uint2(w0, w1);

    {
        __nv_fp8x2_storage_t q0 = __nv_cvt_float2_to_fp8x2(
            make_float2(b0.x*inv_u, b0.y*inv_u), __NV_SATFINITE, __NV_E4M3);
        __nv_fp8x2_storage_t q1 = __nv_cvt_float2_to_fp8x2(
            make_float2(b0.z*inv_u, b0.w*inv_u), __NV_SATFINITE, __NV_E4M3);
        __nv_fp8x2_storage_t q2 = __nv_cvt_float2_to_fp8x2(
            make_float2(b1.x*inv_u, b1.y*inv_u), __NV_SATFINITE, __NV_E4M3);
        __nv_fp8x2_storage_t q3 = __nv_cvt_float2_to_fp8x2(
            make_float2(b1.z*inv_u, b1.w*inv_u), __NV_SATFINITE, __NV_E4M3);
        w0 = (uint32_t)q0 | ((uint32_t)q1 << 16);
        w1 = (uint32_t)q2 | ((uint32_t)q3 << 16);
    }
    reinterpret_cast<uint2*>(g_U8)[(size_t)row * (DDIM / 8) + lane] = make_uint2(w0, w1);
}

// ============================================================================
// Kernel B: fused fp8 mma.sync GEMM (128x128 tile, 2 N-tiles per CTA, K=256)
// + exp + row/col partial sums. 8 warps: warp_m = wid&3, warp_n = wid>>2.
// 2 CTAs/SM (occ=2) so epilogue overlaps neighbor CTA's HMMA.
// ============================================================================
__global__ __launch_bounds__(256, 2) void simloss_mma_kernel()
{
    extern __shared__ __align__(16) char sm[];
    float* rowbuf = reinterpret_cast<float*>(sm + 3 * TILE_BYTES);
    float* colbuf = rowbuf + 128;

    int tid = threadIdx.x, lane = tid & 31, wid = tid >> 5;
    int warp_m = wid & 3, warp_n = wid >> 2;
    int bm = blockIdx.y;        // row-tile (V rows)
    int bx = blockIdx.x;        // pair of column-tiles (U rows)

    if (tid < 128) { rowbuf[tid] = 0.0f; colbuf[tid] = 0.0f; }

    // ---- async loads: A + B0 (group 0), B1 (group 1). 32 KB each. ----
    const char* Ag = reinterpret_cast<const char*>(g_V8) + (size_t)bm * 128 * DDIM;
    const char* Bg = reinterpret_cast<const char*>(g_U8) + (size_t)bx * 256 * DDIM;
    uint32_t As_u  = smem_u32(sm);
    uint32_t Bs_u0 = As_u + TILE_BYTES;
    uint32_t Bs_u1 = As_u + 2 * TILE_BYTES;

    #pragma unroll
    for (int it = 0; it < 8; it++) {
        int i = it * 256 + tid;            // 2048 16B chunks per tile
        int row = i >> 4, c = i & 15;
        uint32_t soff = row * STRIDE_B + c * 16;
        uint32_t goff = row * 256 + c * 16;
        CP_ASYNC16(As_u  + soff, Ag + goff);
        CP_ASYNC16(Bs_u0 + soff, Bg + goff);
    }
    CP_ASYNC_COMMIT();
    #pragma unroll
    for (int it = 0; it < 8; it++) {
        int i = it * 256 + tid;
        int row = i >> 4, c = i & 15;
        CP_ASYNC16(Bs_u1 + row * STRIDE_B + c * 16, Bg + 32768 + row * 256 + c * 16);
    }
    CP_ASYNC_COMMIT();

    // ldmatrix per-lane addresses (fp8 m16n8k32 int8-style fragments)
    // A: row = warp_m*32 + (lane&15), byte = (lane>>4)*16; k-step adds 32B
    uint32_t a_base = As_u + (warp_m * 32 + (lane & 15)) * STRIDE_B + (lane >> 4) * 16;
    // B (n-major rows): row = (lane&7) + ((lane>>4)<<3), byte = ((lane>>3)&1)*16
    uint32_t b_lane_off =
        (warp_n * 64 + (lane & 7) + ((lane >> 4) << 3)) * STRIDE_B + ((lane >> 3) & 1) * 16;

    #pragma unroll 1
    for (int t = 0; t < 2; t++) {
        if (t == 0) { CP_ASYNC_WAIT_1(); } else { CP_ASYNC_WAIT_0(); }
        __syncthreads();

        uint32_t b_base = (t == 0 ? Bs_u0 : Bs_u1) + b_lane_off;

        // ---- mainloop: K = 256 = 8 k-steps of 32 ----
        float acc[64];
        #pragma unroll
        for (int i = 0; i < 64; i++) acc[i] = 0.0f;

        #pragma unroll
        for (int ks = 0; ks < 8; ks++) {
            uint32_t a[2][4];
            ldsm4(a[0], a_base + ks * 32);
            ldsm4(a[1], a_base + ks * 32 + 16 * STRIDE_B);
            uint32_t b[4][4];
            #pragma unroll
            for (int p = 0; p < 4; p++)
                ldsm4(b[p], b_base + ks * 32 + p * 16 * STRIDE_B);
            #pragma unroll
            for (int mt = 0; mt < 2; mt++)
                #pragma unroll
                for (int p = 0; p < 4; p++) {
                    mma_fp8(&acc[(mt * 8 + 2 * p) * 4],     a[mt], &b[p][0]);
                    mma_fp8(&acc[(mt * 8 + 2 * p + 1) * 4], a[mt], &b[p][2]);
                }
        }

        // ---- epilogue: exp + row/col partials ----
        // acc of one m16n8: c0(row g, col 2u), c1(g,2u+1), c2(g+8,2u), c3(g+8,2u+1)
        float rp[4] = {0.f, 0.f, 0.f, 0.f};
        float cp0[8], cp1[8];
        #pragma unroll
        for (int nt = 0; nt < 8; nt++) { cp0[nt] = 0.f; cp1[nt] = 0.f; }

        #pragma unroll
        for (int mt = 0; mt < 2; mt++)
            #pragma unroll
            for (int nt = 0; nt < 8; nt++) {
                float* c = &acc[(mt * 8 + nt) * 4];
                float e0 = __expf(fmaf(c[0], INV_T64, -INV_T));
                float e1 = __expf(fmaf(c[1], INV_T64, -INV_T));
                float e2 = __expf(fmaf(c[2], INV_T64, -INV_T));
                float e3 = __expf(fmaf(c[3], INV_T64, -INV_T));
                rp[mt * 2 + 0] += e0 + e1;
                rp[mt * 2 + 1] += e2 + e3;
                cp0[nt] += e0 + e2;
                cp1[nt] += e1 + e3;
            }

        #pragma unroll
        for (int s = 1; s <= 2; s <<= 1) {
            rp[0] += __shfl_xor_sync(0xffffffffu, rp[0], s);
            rp[1] += __shfl_xor_sync(0xffffffffu, rp[1], s);
            rp[2] += __shfl_xor_sync(0xffffffffu, rp[2], s);
            rp[3] += __shfl_xor_sync(0xffffffffu, rp[3], s);
        }
        if ((lane & 3) == 0) {
            int g = lane >> 2;
            atomicAdd(&rowbuf[warp_m * 32 + g],      rp[0]);
            atomicAdd(&rowbuf[warp_m * 32 + 8 + g],  rp[1]);
            atomicAdd(&rowbuf[warp_m * 32 + 16 + g], rp[2]);
            atomicAdd(&rowbuf[warp_m * 32 + 24 + g], rp[3]);
        }

        #pragma unroll
        for (int s = 4; s <= 16; s <<= 1)
            #pragma unroll
            for (int nt = 0; nt < 8; nt++) {
                cp0[nt] += __shfl_xor_sync(0xffffffffu, cp0[nt], s);
                cp1[nt] += __shfl_xor_sync(0xffffffffu, cp1[nt], s);
            }
        if (lane < 4) {
            int u = lane;
            #pragma unroll
            for (int nt = 0; nt < 8; nt++) {
                atomicAdd(&colbuf[warp_n * 64 + nt * 8 + 2 * u],     cp0[nt]);
                atomicAdd(&colbuf[warp_n * 64 + nt * 8 + 2 * u + 1], cp1[nt]);
            }
        }

        __syncthreads();
        if (tid < 128) {
            atomicAdd(&g_colsum[bx * 256 + t * 128 + tid], colbuf[tid]);
            colbuf[tid] = 0.0f;
        }
        __syncthreads();
    }

    if (tid < 128)
        atomicAdd(&g_rowsum[bm * 128 + tid], rowbuf[tid]);
}

// ============================================================================
// Kernel C: finalize. loss = 1/T + mean(log sum) - (1/T)*mean(diag)
// ============================================================================
__global__ __launch_bounds__(256) void finalize_kernel(float* __restrict__ out)
{
    __shared__ float red_lv[8], red_lu[8], red_d[8];
    int tid = threadIdx.x, lane = tid & 31, warp = tid >> 5;

    float slv = 0.0f, slu = 0.0f, sd = 0.0f;
    for (int i = tid; i < NROWS; i += 256) {
        slv += logf(g_rowsum[i]);
        slu += logf(g_colsum[i]);
        sd  += g_diag[i];
    }
    #pragma unroll
    for (int s = 16; s > 0; s >>= 1) {
        slv += __shfl_xor_sync(0xffffffffu, slv, s);
        slu += __shfl_xor_sync(0xffffffffu, slu, s);
        sd  += __shfl_xor_sync(0xffffffffu, sd,  s);
    }
    if (lane == 0) { red_lv[warp] = slv; red_lu[warp] = slu; red_d[warp] = sd; }
    __syncthreads();
    if (tid == 0) {
        float tlv = 0.0f, tlu = 0.0f, td = 0.0f;
        #pragma unroll
        for (int w = 0; w < 8; w++) { tlv += red_lv[w]; tlu += red_lu[w]; td += red_d[w]; }
        float mlv = tlv * (1.0f / NROWS);
        float mlu = tlu * (1.0f / NROWS);
        float md  = td  * (1.0f / NROWS);
        float loss_vu = INV_T + mlv - INV_T * md;
        float loss_uv = INV_T + mlu - INV_T * md;
        out[0] = 0.5f * loss_vu + 0.5f * loss_uv;
        out[1] = loss_vu;
        out[2] = loss_uv;
    }
}

// ============================================================================
// Launch
// ============================================================================
extern "C" void kernel_launch(void* const* d_in, const int* in_sizes, int n_in,
                              void* d_out, int out_size)
{
    const float* img = (const float*)d_in[0];
    const float* txt = (const float*)d_in[1];
    float* out = (float*)d_out;

    cudaFuncSetAttribute(simloss_mma_kernel,
                         cudaFuncAttributeMaxDynamicSharedMemorySize, SMEM_DYN_BYTES);

    normalize_kernel<<<NROWS / 8, 256>>>(img, txt);
    simloss_mma_kernel<<<dim3(NROWS / 256, NROWS / 128), 256, SMEM_DYN_BYTES>>>();
    finalize_kernel<<<1, 256>>>(out);
}

// round 4
// speedup vs baseline: 1.5900x; 1.2439x over previous
#include <cuda_runtime.h>
#include <cuda_bf16.h>
#include <cuda_fp16.h>
#include <cuda_fp8.h>
#include <cstdint>

// ============================================================================
// Problem constants
// ============================================================================
#define NROWS 16384
#define DDIM  256
#define INV_T 14.285714285714286f        // 1 / 0.07
// y = sim*INV_T*log2(e) - SHIFT2 ; sim = acc/64 -> y = acc*K2 - SHIFT2
#define K2F    0.32203014f               // INV_T*log2e/64
#define SHIFT2 9.0f
#define SHIFT2_LN2 6.23832462504f        // 9*ln(2)

// SMEM tile geometry: fp8, 256 B/row padded to 272 B
#define STRIDE_B 272
#define TILE_BYTES (128 * STRIDE_B)      // 34816 per 128x256 fp8 tile
#define SMEM_DYN_BYTES (3 * TILE_BYTES)  // A + B0 + B1 = 104448

// ============================================================================
// Device scratch
// ============================================================================
__device__ uint8_t g_V8[(size_t)NROWS * DDIM];  // normalized img * 8, e4m3
__device__ uint8_t g_U8[(size_t)NROWS * DDIM];  // normalized txt * 8, e4m3
__device__ float g_rowsum[NROWS];
__device__ float g_colsum[NROWS];
__device__ float g_diag[NROWS];

// ============================================================================
// PTX helpers (baseline sm_89 features -> legal under compute_103)
// ============================================================================
__device__ __forceinline__ uint32_t smem_u32(const void* p) {
    uint32_t a;
    asm("{ .reg .u64 t; cvta.to.shared.u64 t, %1; cvt.u32.u64 %0, t; }"
        : "=r"(a) : "l"(p));
    return a;
}

#define CP_ASYNC16(dst_u32, src_ptr) \
    asm volatile("cp.async.cg.shared.global [%0], [%1], 16;" \
        :: "r"(dst_u32), "l"(src_ptr) : "memory")
#define CP_ASYNC_COMMIT() asm volatile("cp.async.commit_group;" ::: "memory")
#define CP_ASYNC_WAIT_1() asm volatile("cp.async.wait_group 1;" ::: "memory")
#define CP_ASYNC_WAIT_0() asm volatile("cp.async.wait_group 0;" ::: "memory")

__device__ __forceinline__ void ldsm4(uint32_t* r, uint32_t addr) {
    asm volatile("ldmatrix.sync.aligned.m8n8.x4.shared.b16 {%0,%1,%2,%3}, [%4];"
        : "=r"(r[0]), "=r"(r[1]), "=r"(r[2]), "=r"(r[3]) : "r"(addr));
}

// fp8 e4m3 MMA with f16 accumulators: D/C = 2x f16x2 regs
// d0 = {row g: col 2u, col 2u+1}, d1 = {row g+8: col 2u, col 2u+1}
__device__ __forceinline__ void mma_fp8_f16(uint32_t* c, const uint32_t* a, const uint32_t* b) {
    asm volatile(
        "mma.sync.aligned.m16n8k32.row.col.f16.e4m3.e4m3.f16 "
        "{%0,%1}, {%2,%3,%4,%5}, {%6,%7}, {%0,%1};"
        : "+r"(c[0]), "+r"(c[1])
        : "r"(a[0]), "r"(a[1]), "r"(a[2]), "r"(a[3]), "r"(b[0]), "r"(b[1]));
}

__device__ __forceinline__ uint32_t h2exp2(uint32_t y) {
    uint32_t e;
    asm("ex2.approx.f16x2 %0, %1;" : "=r"(e) : "r"(y));
    return e;
}

__device__ __forceinline__ uint32_t h2fma(uint32_t x, uint32_t k, uint32_t b) {
    uint32_t d;
    asm("fma.rn.f16x2 %0, %1, %2, %3;" : "=r"(d) : "r"(x), "r"(k), "r"(b));
    return d;
}

__device__ __forceinline__ uint32_t h2add(uint32_t x, uint32_t y) {
    uint32_t d;
    asm("add.rn.f16x2 %0, %1, %2;" : "=r"(d) : "r"(x), "r"(y));
    return d;
}

__device__ __forceinline__ float h2low(uint32_t h) {
    __half2 v = *reinterpret_cast<__half2*>(&h);
    return __low2float(v);
}
__device__ __forceinline__ float h2high(uint32_t h) {
    __half2 v = *reinterpret_cast<__half2*>(&h);
    return __high2float(v);
}

// ============================================================================
// Kernel A: per-row L2 normalize -> (8*v) as e4m3, diag cos, zero accums
// ============================================================================
__global__ __launch_bounds__(256) void normalize_kernel(
    const float* __restrict__ img, const float* __restrict__ txt)
{
    int warp = threadIdx.x >> 5, lane = threadIdx.x & 31;
    int row = blockIdx.x * 8 + warp;

    const float4* v4 = reinterpret_cast<const float4*>(img) + (size_t)row * (DDIM / 4) + lane * 2;
    const float4* u4 = reinterpret_cast<const float4*>(txt) + (size_t)row * (DDIM / 4) + lane * 2;
    float4 a0 = v4[0], a1 = v4[1];
    float4 b0 = u4[0], b1 = u4[1];

    float sv = a0.x*a0.x + a0.y*a0.y + a0.z*a0.z + a0.w*a0.w
             + a1.x*a1.x + a1.y*a1.y + a1.z*a1.z + a1.w*a1.w;
    float su = b0.x*b0.x + b0.y*b0.y + b0.z*b0.z + b0.w*b0.w
             + b1.x*b1.x + b1.y*b1.y + b1.z*b1.z + b1.w*b1.w;
    float dv = a0.x*b0.x + a0.y*b0.y + a0.z*b0.z + a0.w*b0.w
             + a1.x*b1.x + a1.y*b1.y + a1.z*b1.z + a1.w*b1.w;

    #pragma unroll
    for (int s = 16; s > 0; s >>= 1) {
        sv += __shfl_xor_sync(0xffffffffu, sv, s);
        su += __shfl_xor_sync(0xffffffffu, su, s);
        dv += __shfl_xor_sync(0xffffffffu, dv, s);
    }

    float inv_v = 8.0f / fmaxf(sqrtf(sv), 1e-8f);   // scale x8 into e4m3 range
    float inv_u = 8.0f / fmaxf(sqrtf(su), 1e-8f);

    if (lane == 0) {
        g_diag[row]   = dv * (inv_v * inv_u) * (1.0f / 64.0f);
        g_rowsum[row] = 0.0f;
        g_colsum[row] = 0.0f;
    }

    uint32_t w0, w1;
    {
        __nv_fp8x2_storage_t p0 = __nv_cvt_float2_to_fp8x2(
            make_float2(a0.x*inv_v, a0.y*inv_v), __NV_SATFINITE, __NV_E4M3);
        __nv_fp8x2_storage_t p1 = __nv_cvt_float2_to_fp8x2(
            make_float2(a0.z*inv_v, a0.w*inv_v), __NV_SATFINITE, __NV_E4M3);
        __nv_fp8x2_storage_t p2 = __nv_cvt_float2_to_fp8x2(
            make_float2(a1.x*inv_v, a1.y*inv_v), __NV_SATFINITE, __NV_E4M3);
        __nv_fp8x2_storage_t p3 = __nv_cvt_float2_to_fp8x2(
            make_float2(a1.z*inv_v, a1.w*inv_v), __NV_SATFINITE, __NV_E4M3);
        w0 = (uint32_t)p0 | ((uint32_t)p1 << 16);
        w1 = (uint32_t)p2 | ((uint32_t)p3 << 16);
    }
    reinterpret_cast<uint2*>(g_V8)[(size_t)row * (DDIM / 8) + lane] = make_uint2(w0, w1);

    {
        __nv_fp8x2_storage_t q0 = __nv_cvt_float2_to_fp8x2(
            make_float2(b0.x*inv_u, b0.y*inv_u), __NV_SATFINITE, __NV_E4M3);
        __nv_fp8x2_storage_t q1 = __nv_cvt_float2_to_fp8x2(
            make_float2(b0.z*inv_u, b0.w*inv_u), __NV_SATFINITE, __NV_E4M3);
        __nv_fp8x2_storage_t q2 = __nv_cvt_float2_to_fp8x2(
            make_float2(b1.x*inv_u, b1.y*inv_u), __NV_SATFINITE, __NV_E4M3);
        __nv_fp8x2_storage_t q3 = __nv_cvt_float2_to_fp8x2(
            make_float2(b1.z*inv_u, b1.w*inv_u), __NV_SATFINITE, __NV_E4M3);
        w0 = (uint32_t)q0 | ((uint32_t)q1 << 16);
        w1 = (uint32_t)q2 | ((uint32_t)q3 << 16);
    }
    reinterpret_cast<uint2*>(g_U8)[(size_t)row * (DDIM / 8) + lane] = make_uint2(w0, w1);
}

// ============================================================================
// Kernel B: fused fp8 GEMM, f16 acc, 2 N-tiles per CTA back-to-back,
// single fp16x2 epilogue, direct global atomics. 8 warps, 2 CTAs/SM.
// ============================================================================
__global__ __launch_bounds__(256, 2) void simloss_mma_kernel()
{
    extern __shared__ __align__(16) char smbuf[];

    int tid = threadIdx.x, lane = tid & 31, wid = tid >> 5;
    int warp_m = wid & 3, warp_n = wid >> 2;
    int bm = blockIdx.y;        // row-tile (V rows)
    int bx = blockIdx.x;        // pair of column-tiles (U rows)

    // ---- async loads: A + B0 (group 0), B1 (group 1) ----
    const char* Ag = reinterpret_cast<const char*>(g_V8) + (size_t)bm * 128 * DDIM;
    const char* Bg = reinterpret_cast<const char*>(g_U8) + (size_t)bx * 256 * DDIM;
    uint32_t As_u  = smem_u32(smbuf);
    uint32_t Bs_u0 = As_u + TILE_BYTES;
    uint32_t Bs_u1 = As_u + 2 * TILE_BYTES;

    #pragma unroll
    for (int it = 0; it < 8; it++) {
        int i = it * 256 + tid;
        int row = i >> 4, c = i & 15;
        uint32_t soff = row * STRIDE_B + c * 16;
        uint32_t goff = row * 256 + c * 16;
        CP_ASYNC16(As_u  + soff, Ag + goff);
        CP_ASYNC16(Bs_u0 + soff, Bg + goff);
    }
    CP_ASYNC_COMMIT();
    #pragma unroll
    for (int it = 0; it < 8; it++) {
        int i = it * 256 + tid;
        int row = i >> 4, c = i & 15;
        CP_ASYNC16(Bs_u1 + row * STRIDE_B + c * 16, Bg + 32768 + row * 256 + c * 16);
    }
    CP_ASYNC_COMMIT();

    // ldmatrix per-lane addresses
    uint32_t a_base = As_u + (warp_m * 32 + (lane & 15)) * STRIDE_B + (lane >> 4) * 16;
    uint32_t b_lane_off =
        (warp_n * 64 + (lane & 7) + ((lane >> 4) << 3)) * STRIDE_B + ((lane >> 3) & 1) * 16;

    // acc: [t][mt*8+nt][2] f16x2 regs
    uint32_t acc[64];
    #pragma unroll
    for (int i = 0; i < 64; i++) acc[i] = 0u;

    // ---- mainloop t=0 ----
    CP_ASYNC_WAIT_1();
    __syncthreads();
    {
        uint32_t b_base = Bs_u0 + b_lane_off;
        #pragma unroll
        for (int ks = 0; ks < 8; ks++) {
            uint32_t a[2][4];
            ldsm4(a[0], a_base + ks * 32);
            ldsm4(a[1], a_base + ks * 32 + 16 * STRIDE_B);
            uint32_t b[4][4];
            #pragma unroll
            for (int p = 0; p < 4; p++)
                ldsm4(b[p], b_base + ks * 32 + p * 16 * STRIDE_B);
            #pragma unroll
            for (int mt = 0; mt < 2; mt++)
                #pragma unroll
                for (int p = 0; p < 4; p++) {
                    mma_fp8_f16(&acc[(mt * 8 + 2 * p) * 2],     a[mt], &b[p][0]);
                    mma_fp8_f16(&acc[(mt * 8 + 2 * p + 1) * 2], a[mt], &b[p][2]);
                }
        }
    }

    // ---- mainloop t=1 ----
    CP_ASYNC_WAIT_0();
    __syncthreads();
    {
        uint32_t b_base = Bs_u1 + b_lane_off;
        #pragma unroll
        for (int ks = 0; ks < 8; ks++) {
            uint32_t a[2][4];
            ldsm4(a[0], a_base + ks * 32);
            ldsm4(a[1], a_base + ks * 32 + 16 * STRIDE_B);
            uint32_t b[4][4];
            #pragma unroll
            for (int p = 0; p < 4; p++)
                ldsm4(b[p], b_base + ks * 32 + p * 16 * STRIDE_B);
            #pragma unroll
            for (int mt = 0; mt < 2; mt++)
                #pragma unroll
                for (int p = 0; p < 4; p++) {
                    mma_fp8_f16(&acc[32 + (mt * 8 + 2 * p) * 2],     a[mt], &b[p][0]);
                    mma_fp8_f16(&acc[32 + (mt * 8 + 2 * p + 1) * 2], a[mt], &b[p][2]);
                }
        }
    }

    // ---- combined epilogue: y = acc*K2 - 9 ; e = 2^y ; fp16x2 sums ----
    __half2 hk = __half2half2(__float2half_rn(K2F));
    __half2 hs = __half2half2(__float2half_rn(-SHIFT2));
    uint32_t K2u = *reinterpret_cast<uint32_t*>(&hk);
    uint32_t S2u = *reinterpret_cast<uint32_t*>(&hs);

    uint32_t rpa[2] = {0u, 0u};   // rows (16mt+g): halves = partial over col pairs
    uint32_t rpb[2] = {0u, 0u};   // rows (16mt+8+g)
    uint32_t cph[16];             // [t*8+nt]: (col 2u, col 2u+1) sums over 4 rows
    #pragma unroll
    for (int i = 0; i < 16; i++) cph[i] = 0u;

    #pragma unroll
    for (int t = 0; t < 2; t++)
        #pragma unroll
        for (int mt = 0; mt < 2; mt++)
            #pragma unroll
            for (int nt = 0; nt < 8; nt++) {
                int idx = t * 32 + (mt * 8 + nt) * 2;
                uint32_t e0 = h2exp2(h2fma(acc[idx],     K2u, S2u));  // row g
                uint32_t e1 = h2exp2(h2fma(acc[idx + 1], K2u, S2u));  // row g+8
                rpa[mt] = h2add(rpa[mt], e0);
                rpb[mt] = h2add(rpb[mt], e1);
                cph[t * 8 + nt] = h2add(cph[t * 8 + nt], h2add(e0, e1));
            }

    // row reduce across the 4 u-lanes
    #pragma unroll
    for (int s = 1; s <= 2; s <<= 1) {
        #pragma unroll
        for (int mt = 0; mt < 2; mt++) {
            rpa[mt] = h2add(rpa[mt], __shfl_xor_sync(0xffffffffu, rpa[mt], s));
            rpb[mt] = h2add(rpb[mt], __shfl_xor_sync(0xffffffffu, rpb[mt], s));
        }
    }
    if ((lane & 3) == 0) {
        int g = lane >> 2;
        #pragma unroll
        for (int mt = 0; mt < 2; mt++) {
            int r = bm * 128 + warp_m * 32 + mt * 16 + g;
            atomicAdd(&g_rowsum[r],     h2low(rpa[mt]) + h2high(rpa[mt]));
            atomicAdd(&g_rowsum[r + 8], h2low(rpb[mt]) + h2high(rpb[mt]));
        }
    }

    // col reduce across the 8 g-groups
    #pragma unroll
    for (int s = 4; s <= 16; s <<= 1)
        #pragma unroll
        for (int i = 0; i < 16; i++)
            cph[i] = h2add(cph[i], __shfl_xor_sync(0xffffffffu, cph[i], s));
    if (lane < 4) {
        int u = lane;
        #pragma unroll
        for (int t = 0; t < 2; t++)
            #pragma unroll
            for (int nt = 0; nt < 8; nt++) {
                int cb = bx * 256 + t * 128 + warp_n * 64 + nt * 8 + 2 * u;
                atomicAdd(&g_colsum[cb],     h2low(cph[t * 8 + nt]));
                atomicAdd(&g_colsum[cb + 1], h2high(cph[t * 8 + nt]));
            }
    }
}

// ============================================================================
// Kernel C: finalize. loss = 9ln2 + mean(log sum) - (1/T)*mean(diag)
// ============================================================================
__global__ __launch_bounds__(256) void finalize_kernel(float* __restrict__ out)
{
    __shared__ float red_lv[8], red_lu[8], red_d[8];
    int tid = threadIdx.x, lane = tid & 31, warp = tid >> 5;

    float slv = 0.0f, slu = 0.0f, sd = 0.0f;
    for (int i = tid; i < NROWS; i += 256) {
        slv += logf(g_rowsum[i]);
        slu += logf(g_colsum[i]);
        sd  += g_diag[i];
    }
    #pragma unroll
    for (int s = 16; s > 0; s >>= 1) {
        slv += __shfl_xor_sync(0xffffffffu, slv, s);
        slu += __shfl_xor_sync(0xffffffffu, slu, s);
        sd  += __shfl_xor_sync(0xffffffffu, sd,  s);
    }
    if (lane == 0) { red_lv[warp] = slv; red_lu[warp] = slu; red_d[warp] = sd; }
    __syncthreads();
    if (tid == 0) {
        float tlv = 0.0f, tlu = 0.0f, td = 0.0f;
        #pragma unroll
        for (int w = 0; w < 8; w++) { tlv += red_lv[w]; tlu += red_lu[w]; td += red_d[w]; }
        float mlv = tlv * (1.0f / NROWS);
        float mlu = tlu * (1.0f / NROWS);
        float md  = td  * (1.0f / NROWS);
        float loss_vu = SHIFT2_LN2 + mlv - INV_T * md;
        float loss_uv = SHIFT2_LN2 + mlu - INV_T * md;
        out[0] = 0.5f * loss_vu + 0.5f * loss_uv;
        out[1] = loss_vu;
        out[2] = loss_uv;
    }
}

// ============================================================================
// Launch
// ============================================================================
extern "C" void kernel_launch(void* const* d_in, const int* in_sizes, int n_in,
                              void* d_out, int out_size)
{
    const float* img = (const float*)d_in[0];
    const float* txt = (const float*)d_in[1];
    float* out = (float*)d_out;

    cudaFuncSetAttribute(simloss_mma_kernel,
                         cudaFuncAttributeMaxDynamicSharedMemorySize, SMEM_DYN_BYTES);

    normalize_kernel<<<NROWS / 8, 256>>>(img, txt);
    simloss_mma_kernel<<<dim3(NROWS / 256, NROWS / 128), 256, SMEM_DYN_BYTES>>>();
    finalize_kernel<<<1, 256>>>(out);
}